// round 2
// baseline (speedup 1.0000x reference)
#include <cuda_runtime.h>
#include <math.h>

#define BB 2
#define TT 2048
#define CC 1024
#define HH 16
#define DD 64
#define MM (BB*TT)   // 4096 rows

// Scratch (allocation-free rule: __device__ globals)
__device__ float g_q[BB*HH*TT*DD];   // [B,H,T,D]
__device__ float g_k[BB*HH*TT*DD];
__device__ float g_v[BB*HH*TT*DD];
__device__ float g_y[BB*TT*CC];      // attention output, [B,T,C]

// ---------------------------------------------------------------------------
// Tiled fp32 GEMM core: C[64x64] tile of  out = A[M,K] @ W[N,K]^T
// 256 threads, 4x4 register blocking, BK=16.
// ---------------------------------------------------------------------------

__global__ __launch_bounds__(256) void qkv_gemm(
    const float* __restrict__ x,
    const float* __restrict__ Wq, const float* __restrict__ bq,
    const float* __restrict__ Wk, const float* __restrict__ bk,
    const float* __restrict__ Wv, const float* __restrict__ bv)
{
    const float* W;
    const float* bias;
    float* out;
    if (blockIdx.z == 0)      { W = Wq; bias = bq; out = g_q; }
    else if (blockIdx.z == 1) { W = Wk; bias = bk; out = g_k; }
    else                      { W = Wv; bias = bv; out = g_v; }

    __shared__ float As[16][68];
    __shared__ float Bs[16][68];

    const int tid = threadIdx.x;
    const int tr  = tid >> 4;          // 0..15  (row group)
    const int tc  = tid & 15;          // 0..15  (col group)
    const int m0  = blockIdx.y << 6;
    const int n0  = blockIdx.x << 6;
    const int lm  = tid >> 2;          // 0..63  (load row)
    const int lk  = (tid & 3) << 2;    // 0,4,8,12 (load k)

    const float* ag = x + (size_t)(m0 + lm) * CC + lk;
    const float* bg = W + (size_t)(n0 + lm) * CC + lk;

    float acc[4][4] = {};

    for (int k0 = 0; k0 < CC; k0 += 16) {
        float4 a = *(const float4*)(ag + k0);
        float4 b = *(const float4*)(bg + k0);
        __syncthreads();
        As[lk+0][lm] = a.x; As[lk+1][lm] = a.y; As[lk+2][lm] = a.z; As[lk+3][lm] = a.w;
        Bs[lk+0][lm] = b.x; Bs[lk+1][lm] = b.y; Bs[lk+2][lm] = b.z; Bs[lk+3][lm] = b.w;
        __syncthreads();
        #pragma unroll
        for (int kk = 0; kk < 16; kk++) {
            float4 av = *(const float4*)&As[kk][tr << 2];
            float4 bv4 = *(const float4*)&Bs[kk][tc << 2];
            float aa[4] = {av.x, av.y, av.z, av.w};
            float bbv[4] = {bv4.x, bv4.y, bv4.z, bv4.w};
            #pragma unroll
            for (int i = 0; i < 4; i++)
                #pragma unroll
                for (int j = 0; j < 4; j++)
                    acc[i][j] += aa[i] * bbv[j];
        }
    }

    float4 bl = *(const float4*)&bias[n0 + (tc << 2)];
    const float bb[4] = {bl.x, bl.y, bl.z, bl.w};

    const int h = blockIdx.x;          // N=1024, 64-wide tiles -> head index
    #pragma unroll
    for (int i = 0; i < 4; i++) {
        int m = m0 + (tr << 2) + i;
        int b = m >> 11;               // /2048
        int t = m & 2047;
        float4 o;
        o.x = acc[i][0] + bb[0];
        o.y = acc[i][1] + bb[1];
        o.z = acc[i][2] + bb[2];
        o.w = acc[i][3] + bb[3];
        *(float4*)&out[(((size_t)(b*HH + h) * TT + t) * DD) + (tc << 2)] = o;
    }
}

// Output projection: out[M,N] = g_y[M,K] @ Wo[N,K]^T + bo, plain layout.
__global__ __launch_bounds__(256) void out_gemm(
    const float* __restrict__ Wo, const float* __restrict__ bo,
    float* __restrict__ out)
{
    __shared__ float As[16][68];
    __shared__ float Bs[16][68];

    const int tid = threadIdx.x;
    const int tr  = tid >> 4;
    const int tc  = tid & 15;
    const int m0  = blockIdx.y << 6;
    const int n0  = blockIdx.x << 6;
    const int lm  = tid >> 2;
    const int lk  = (tid & 3) << 2;

    const float* ag = g_y + (size_t)(m0 + lm) * CC + lk;
    const float* bg = Wo  + (size_t)(n0 + lm) * CC + lk;

    float acc[4][4] = {};

    for (int k0 = 0; k0 < CC; k0 += 16) {
        float4 a = *(const float4*)(ag + k0);
        float4 b = *(const float4*)(bg + k0);
        __syncthreads();
        As[lk+0][lm] = a.x; As[lk+1][lm] = a.y; As[lk+2][lm] = a.z; As[lk+3][lm] = a.w;
        Bs[lk+0][lm] = b.x; Bs[lk+1][lm] = b.y; Bs[lk+2][lm] = b.z; Bs[lk+3][lm] = b.w;
        __syncthreads();
        #pragma unroll
        for (int kk = 0; kk < 16; kk++) {
            float4 av = *(const float4*)&As[kk][tr << 2];
            float4 bv4 = *(const float4*)&Bs[kk][tc << 2];
            float aa[4] = {av.x, av.y, av.z, av.w};
            float bbv[4] = {bv4.x, bv4.y, bv4.z, bv4.w};
            #pragma unroll
            for (int i = 0; i < 4; i++)
                #pragma unroll
                for (int j = 0; j < 4; j++)
                    acc[i][j] += aa[i] * bbv[j];
        }
    }

    float4 bl = *(const float4*)&bo[n0 + (tc << 2)];
    const float bb[4] = {bl.x, bl.y, bl.z, bl.w};

    #pragma unroll
    for (int i = 0; i < 4; i++) {
        int m = m0 + (tr << 2) + i;
        float4 o;
        o.x = acc[i][0] + bb[0];
        o.y = acc[i][1] + bb[1];
        o.z = acc[i][2] + bb[2];
        o.w = acc[i][3] + bb[3];
        *(float4*)&out[(size_t)m * CC + n0 + (tc << 2)] = o;
    }
}

// ---------------------------------------------------------------------------
// Flash attention, fp32, online softmax. Grid: (T/64, B*H). Block: 256.
// FIX (R2): tile loads now cover the full 64-dim axis (4 float4 per thread).
// ---------------------------------------------------------------------------
#define FLASH_SMEM_FLOATS (2*64*68 + 64*64)

__global__ __launch_bounds__(256) void flash64()
{
    extern __shared__ float sm[];
    float* Qt   = sm;              // [d][q], stride 68
    float* KtPs = sm + 64*68;      // Kt: [d][k] stride 68; Ps: [q][k] stride 68
    float* Vs   = sm + 2*64*68;    // [k][d], stride 64

    const int tid = threadIdx.x;
    const int tr  = tid >> 4;      // query row group (4 rows each)
    const int tc  = tid & 15;      // key/d col group (4 cols each)
    const int q0  = blockIdx.x << 6;
    const int bh  = blockIdx.y;

    const float* qg = g_q + ((size_t)bh * TT + q0) * DD;
    const float* kg = g_k + (size_t)bh * TT * DD;
    const float* vg = g_v + (size_t)bh * TT * DD;

    const int tl = tid >> 2;           // 0..63 load row
    const int d4 = (tid & 3) << 2;     // 0,4,8,12 (+ dd stride of 16)

    // Load Q transposed (d-major), pre-scaled by 1/sqrt(64).
    #pragma unroll
    for (int dd = 0; dd < 64; dd += 16) {
        float4 v = *(const float4*)(qg + tl * DD + dd + d4);
        Qt[(dd+d4+0)*68 + tl] = v.x * 0.125f;
        Qt[(dd+d4+1)*68 + tl] = v.y * 0.125f;
        Qt[(dd+d4+2)*68 + tl] = v.z * 0.125f;
        Qt[(dd+d4+3)*68 + tl] = v.w * 0.125f;
    }

    float m_run[4], l_run[4], acc[4][4];
    #pragma unroll
    for (int i = 0; i < 4; i++) {
        m_run[i] = -1e30f;
        l_run[i] = 0.f;
        #pragma unroll
        for (int j = 0; j < 4; j++) acc[i][j] = 0.f;
    }

    const int jmax = q0 >> 6;
    for (int jt = 0; jt <= jmax; jt++) {
        __syncthreads();   // previous iteration's Ps/Vs reads done
        #pragma unroll
        for (int dd = 0; dd < 64; dd += 16) {
            float4 kv = *(const float4*)(kg + (size_t)((jt<<6) + tl) * DD + dd + d4);
            KtPs[(dd+d4+0)*68 + tl] = kv.x;
            KtPs[(dd+d4+1)*68 + tl] = kv.y;
            KtPs[(dd+d4+2)*68 + tl] = kv.z;
            KtPs[(dd+d4+3)*68 + tl] = kv.w;
            float4 vv = *(const float4*)(vg + (size_t)((jt<<6) + tl) * DD + dd + d4);
            *(float4*)&Vs[tl*64 + dd + d4] = vv;
        }
        __syncthreads();

        // S = (Q*scale) @ K^T   (both operands d-major in smem)
        float s[4][4] = {};
        #pragma unroll 16
        for (int d = 0; d < 64; d++) {
            float4 a = *(const float4*)&Qt[d*68 + (tr << 2)];
            float4 b = *(const float4*)&KtPs[d*68 + (tc << 2)];
            float aa[4] = {a.x, a.y, a.z, a.w};
            float bbv[4] = {b.x, b.y, b.z, b.w};
            #pragma unroll
            for (int i = 0; i < 4; i++)
                #pragma unroll
                for (int j = 0; j < 4; j++)
                    s[i][j] += aa[i] * bbv[j];
        }

        // causal mask on the diagonal tile
        if (jt == jmax) {
            #pragma unroll
            for (int i = 0; i < 4; i++) {
                int qgl = q0 + (tr << 2) + i;
                #pragma unroll
                for (int j = 0; j < 4; j++) {
                    int kgl = (jt << 6) + (tc << 2) + j;
                    if (kgl > qgl) s[i][j] = -1e30f;
                }
            }
        }

        // online softmax: row max / exp / row sum (16-lane group reductions)
        float mnew[4], rs[4], p[4][4];
        #pragma unroll
        for (int i = 0; i < 4; i++) {
            float rm = fmaxf(fmaxf(s[i][0], s[i][1]), fmaxf(s[i][2], s[i][3]));
            rm = fmaxf(rm, __shfl_xor_sync(0xffffffffu, rm, 8, 16));
            rm = fmaxf(rm, __shfl_xor_sync(0xffffffffu, rm, 4, 16));
            rm = fmaxf(rm, __shfl_xor_sync(0xffffffffu, rm, 2, 16));
            rm = fmaxf(rm, __shfl_xor_sync(0xffffffffu, rm, 1, 16));
            mnew[i] = fmaxf(m_run[i], rm);
            float sum = 0.f;
            #pragma unroll
            for (int j = 0; j < 4; j++) {
                p[i][j] = __expf(s[i][j] - mnew[i]);
                sum += p[i][j];
            }
            sum += __shfl_xor_sync(0xffffffffu, sum, 8, 16);
            sum += __shfl_xor_sync(0xffffffffu, sum, 4, 16);
            sum += __shfl_xor_sync(0xffffffffu, sum, 2, 16);
            sum += __shfl_xor_sync(0xffffffffu, sum, 1, 16);
            rs[i] = sum;
        }

        __syncthreads();   // all Kt reads done -> safe to overwrite with Ps

        #pragma unroll
        for (int i = 0; i < 4; i++) {
            float4 pv = make_float4(p[i][0], p[i][1], p[i][2], p[i][3]);
            *(float4*)&KtPs[((tr << 2) + i) * 68 + (tc << 2)] = pv;
        }

        __syncthreads();   // Ps visible to all

        // rescale running stats + accumulate O += P @ V
        #pragma unroll
        for (int i = 0; i < 4; i++) {
            float alpha = __expf(m_run[i] - mnew[i]);
            m_run[i] = mnew[i];
            l_run[i] = l_run[i] * alpha + rs[i];
            #pragma unroll
            for (int j = 0; j < 4; j++) acc[i][j] *= alpha;
        }
        #pragma unroll 16
        for (int kk = 0; kk < 64; kk++) {
            float aa[4];
            #pragma unroll
            for (int i = 0; i < 4; i++)
                aa[i] = KtPs[((tr << 2) + i) * 68 + kk];
            float4 b = *(const float4*)&Vs[kk*64 + (tc << 2)];
            float bbv[4] = {b.x, b.y, b.z, b.w};
            #pragma unroll
            for (int i = 0; i < 4; i++)
                #pragma unroll
                for (int j = 0; j < 4; j++)
                    acc[i][j] += aa[i] * bbv[j];
        }
    }

    // epilogue: normalize and write to g_y in [B,T,C] layout
    const int b = bh >> 4;
    const int h = bh & 15;
    #pragma unroll
    for (int i = 0; i < 4; i++) {
        float inv = 1.f / l_run[i];
        int t = q0 + (tr << 2) + i;
        float4 o;
        o.x = acc[i][0] * inv;
        o.y = acc[i][1] * inv;
        o.z = acc[i][2] * inv;
        o.w = acc[i][3] * inv;
        *(float4*)&g_y[((size_t)(b*TT + t)) * CC + h*DD + (tc << 2)] = o;
    }
}

// ---------------------------------------------------------------------------

extern "C" void kernel_launch(void* const* d_in, const int* in_sizes, int n_in,
                              void* d_out, int out_size)
{
    const float* x  = (const float*)d_in[0];
    const float* Wq = (const float*)d_in[1];
    const float* bq = (const float*)d_in[2];
    const float* Wk = (const float*)d_in[3];
    const float* bk = (const float*)d_in[4];
    const float* Wv = (const float*)d_in[5];
    const float* bv = (const float*)d_in[6];
    const float* Wo = (const float*)d_in[7];
    const float* bo = (const float*)d_in[8];
    float* out = (float*)d_out;

    // 1) QKV projections -> g_q/g_k/g_v in [B,H,T,D]
    dim3 gq(CC/64, MM/64, 3);
    qkv_gemm<<<gq, 256>>>(x, Wq, bq, Wk, bk, Wv, bv);

    // 2) causal flash attention -> g_y in [B,T,C]
    const int smem_bytes = FLASH_SMEM_FLOATS * (int)sizeof(float);
    cudaFuncSetAttribute(flash64, cudaFuncAttributeMaxDynamicSharedMemorySize,
                         smem_bytes);
    flash64<<<dim3(TT/64, BB*HH), 256, smem_bytes>>>();

    // 3) output projection -> d_out
    out_gemm<<<dim3(CC/64, MM/64), 256>>>(Wo, bo, out);
}

// round 4
// speedup vs baseline: 1.6552x; 1.6552x over previous
#include <cuda_runtime.h>
#include <cuda_bf16.h>
#include <cstdint>
#include <math.h>

#define BB 2
#define TT 2048
#define CC 1024
#define HH 16
#define DD 64
#define MM (BB*TT)   // 4096 rows

// ---------------------------------------------------------------------------
// Scratch (__device__ globals; allocation-free rule)
// ---------------------------------------------------------------------------
__device__ float g_q[BB*HH*TT*DD];   // [B,H,T,D]
__device__ float g_k[BB*HH*TT*DD];
__device__ float g_v[BB*HH*TT*DD];
__device__ float g_y[BB*TT*CC];      // attention output, [B,T,C]

__device__ __nv_bfloat16 g_xhi[MM*CC], g_xlo[MM*CC];        // x split
__device__ __nv_bfloat16 g_whi[3*CC*CC], g_wlo[3*CC*CC];    // Wq|Wk|Wv concat
__device__ __nv_bfloat16 g_wohi[CC*CC], g_wolo[CC*CC];      // Wo
__device__ __nv_bfloat16 g_yhi[MM*CC], g_ylo[MM*CC];        // y split
__device__ float g_bqkv[3*CC];                               // bq|bk|bv concat

// ---------------------------------------------------------------------------
// Helpers: ldmatrix / mma.sync (baseline sm_80+, compiles for compute_103)
// ---------------------------------------------------------------------------
__device__ __forceinline__ uint32_t smem_to_u32(const void* p) {
    uint32_t a;
    asm("{ .reg .u64 t; cvta.to.shared.u64 t, %1; cvt.u32.u64 %0, t; }"
        : "=r"(a) : "l"(p));
    return a;
}

__device__ __forceinline__ void ldsm_x4(uint32_t* r, uint32_t addr) {
    asm volatile("ldmatrix.sync.aligned.m8n8.x4.shared.b16 {%0,%1,%2,%3}, [%4];"
        : "=r"(r[0]), "=r"(r[1]), "=r"(r[2]), "=r"(r[3]) : "r"(addr));
}

__device__ __forceinline__ void mma_bf16(float* d, const uint32_t* a,
                                         const uint32_t* b) {
    asm volatile(
        "mma.sync.aligned.m16n8k16.row.col.f32.bf16.bf16.f32 "
        "{%0,%1,%2,%3}, {%4,%5,%6,%7}, {%8,%9}, {%0,%1,%2,%3};"
        : "+f"(d[0]), "+f"(d[1]), "+f"(d[2]), "+f"(d[3])
        : "r"(a[0]), "r"(a[1]), "r"(a[2]), "r"(a[3]), "r"(b[0]), "r"(b[1]));
}

__device__ __forceinline__ void cp16(uint32_t saddr, const void* g) {
    asm volatile("cp.async.cg.shared.global [%0], [%1], 16;"
        :: "r"(saddr), "l"(g) : "memory");
}
#define CP_COMMIT()  asm volatile("cp.async.commit_group;" ::: "memory")
#define CP_WAIT1()   asm volatile("cp.async.wait_group 1;" ::: "memory")
#define CP_WAIT0()   asm volatile("cp.async.wait_group 0;" ::: "memory")

#define SMEM_SWIZZLE_128B(byte_offset) \
    ((byte_offset) ^ (((byte_offset) >> 3) & 0x70))

// ---------------------------------------------------------------------------
// Prep: fp32 -> bf16 hi/lo splits, bias concat.
// ---------------------------------------------------------------------------
__global__ __launch_bounds__(256) void prep_split(
    const float* __restrict__ Wq, const float* __restrict__ Wk,
    const float* __restrict__ Wv, const float* __restrict__ Wo,
    const float* __restrict__ x)
{
    const int i = blockIdx.x * 256 + threadIdx.x;   // 0 .. 8M-1
    const int WQKV = 3*CC*CC, WO = CC*CC;
    float v;
    __nv_bfloat16 *hi, *lo;
    int j;
    if (i < WQKV) {
        const float* s = (i < CC*CC) ? Wq : (i < 2*CC*CC) ? Wk : Wv;
        v = s[i & (CC*CC - 1)];
        hi = g_whi; lo = g_wlo; j = i;
    } else if (i < WQKV + WO) {
        j = i - WQKV;
        v = Wo[j];
        hi = g_wohi; lo = g_wolo;
    } else {
        j = i - WQKV - WO;      // 0 .. 4M-1
        v = x[j];
        hi = g_xhi; lo = g_xlo;
    }
    __nv_bfloat16 h = __float2bfloat16(v);
    hi[j] = h;
    lo[j] = __float2bfloat16(v - __bfloat162float(h));
}

__global__ void prep_bias(const float* __restrict__ bq,
                          const float* __restrict__ bk,
                          const float* __restrict__ bv)
{
    int i = blockIdx.x * 256 + threadIdx.x;
    if (i < 3*CC)
        g_bqkv[i] = (i < CC) ? bq[i] : (i < 2*CC) ? bk[i-CC] : bv[i-2*CC];
}

__global__ __launch_bounds__(256) void prep_y()
{
    const int i = blockIdx.x * 256 + threadIdx.x;   // 0 .. 4M-1
    float v = g_y[i];
    __nv_bfloat16 h = __float2bfloat16(v);
    g_yhi[i] = h;
    g_ylo[i] = __float2bfloat16(v - __bfloat162float(h));
}

// ---------------------------------------------------------------------------
// mma.sync GEMM: D[128x128] tile of A[M,1024] @ B[N,1024]^T, bf16 hi/lo
// 3-term, fp32 accum in registers. cp.async double-buffered smem, SW128.
// 8 warps in 4(M)x2(N): warp tile 32x64.
// mode 0: A=x, B=WqWkWv concat, scatter to g_q/g_k/g_v (+bias).
// mode 1: A=y, B=Wo, write d_out (+bo).
// ---------------------------------------------------------------------------
#define CHUNK_K   64
#define NCHUNK    (CC / CHUNK_K)      // 16
#define BUF_BYTES (128*64*2)          // 16 KB per operand buffer
#define STAGE_BYTES (4*BUF_BYTES)     // 64 KB
#define OFF_AH 0
#define OFF_AL (1*BUF_BYTES)
#define OFF_BH (2*BUF_BYTES)
#define OFF_BL (3*BUF_BYTES)
#define GEMM_SMEM (2*STAGE_BYTES + 1024)

__global__ __launch_bounds__(256, 1) void gemm_tc(
    int mode, const float* __restrict__ bias1, float* __restrict__ outf)
{
    extern __shared__ char smem[];
    const uint32_t smem_u32 = smem_to_u32(smem);
    const uint32_t tile_u32 = (smem_u32 + 1023) & ~1023u;

    const int tid  = threadIdx.x;
    const int wid  = tid >> 5;
    const int lane = tid & 31;
    const int wm   = wid >> 1;          // 0..3 (M)
    const int wn   = wid & 1;           // 0..1 (N)
    const int m0   = blockIdx.y << 7;
    const int n0   = blockIdx.x << 7;

    const __nv_bfloat16 *Ah, *Al, *Bh, *Bl;
    if (mode == 0) { Ah = g_xhi; Al = g_xlo; Bh = g_whi;  Bl = g_wlo;  }
    else           { Ah = g_yhi; Al = g_ylo; Bh = g_wohi; Bl = g_wolo; }

    // --- async chunk loader: 16 cp.async(16B) per thread per chunk ---
    auto issue_chunk = [&](int c, int s) {
        const int kc = c * CHUNK_K;
        const uint32_t st = tile_u32 + s * STAGE_BYTES;
        #pragma unroll
        for (int i = 0; i < 4; i++) {
            int idx = tid + i*256;           // 0..1023
            int r   = idx >> 3;              // tile row 0..127
            int g   = idx & 7;               // 16B group in row
            uint32_t so = SMEM_SWIZZLE_128B((uint32_t)(r*128 + g*16));
            size_t aoff = (size_t)(m0 + r) * CC + kc + g*8;
            size_t boff = (size_t)(n0 + r) * CC + kc + g*8;
            cp16(st + OFF_AH + so, Ah + aoff);
            cp16(st + OFF_AL + so, Al + aoff);
            cp16(st + OFF_BH + so, Bh + boff);
            cp16(st + OFF_BL + so, Bl + boff);
        }
        CP_COMMIT();
    };

    float acc[2][8][4];
    #pragma unroll
    for (int mt = 0; mt < 2; mt++)
        #pragma unroll
        for (int nt = 0; nt < 8; nt++)
            #pragma unroll
            for (int e = 0; e < 4; e++) acc[mt][nt][e] = 0.f;

    issue_chunk(0, 0);
    issue_chunk(1, 1);

    for (int c = 0; c < NCHUNK; ++c) {
        const int s = c & 1;
        if (c + 1 < NCHUNK) { CP_WAIT1(); } else { CP_WAIT0(); }
        __syncthreads();

        const uint32_t sAh = tile_u32 + s*STAGE_BYTES + OFF_AH;
        const uint32_t sAl = tile_u32 + s*STAGE_BYTES + OFF_AL;
        const uint32_t sBh = tile_u32 + s*STAGE_BYTES + OFF_BH;
        const uint32_t sBl = tile_u32 + s*STAGE_BYTES + OFF_BL;

        #pragma unroll
        for (int ks = 0; ks < 4; ++ks) {
            // A fragments (hi+lo), two 16-row tiles
            uint32_t ah[2][4], al[2][4];
            #pragma unroll
            for (int mt = 0; mt < 2; ++mt) {
                int r = wm*32 + mt*16 + (lane & 15);
                int g = ks*2 + (lane >> 4);
                uint32_t off = SMEM_SWIZZLE_128B((uint32_t)(r*128 + g*16));
                ldsm_x4(ah[mt], sAh + off);
                ldsm_x4(al[mt], sAl + off);
            }
            #pragma unroll
            for (int np = 0; np < 4; ++np) {
                int n = wn*64 + np*16 + ((lane >> 4) << 3) + (lane & 7);
                int g = ks*2 + ((lane >> 3) & 1);
                uint32_t off = SMEM_SWIZZLE_128B((uint32_t)(n*128 + g*16));
                uint32_t bh[4], bl[4];
                ldsm_x4(bh, sBh + off);
                ldsm_x4(bl, sBl + off);
                #pragma unroll
                for (int mt = 0; mt < 2; ++mt) {
                    mma_bf16(acc[mt][2*np],   ah[mt], bh);
                    mma_bf16(acc[mt][2*np+1], ah[mt], bh + 2);
                    mma_bf16(acc[mt][2*np],   ah[mt], bl);
                    mma_bf16(acc[mt][2*np+1], ah[mt], bl + 2);
                    mma_bf16(acc[mt][2*np],   al[mt], bh);
                    mma_bf16(acc[mt][2*np+1], al[mt], bh + 2);
                }
            }
        }

        if (c + 2 < NCHUNK) {
            __syncthreads();           // all warps done reading buffer s
            issue_chunk(c + 2, s);
        }
    }

    // --- epilogue: write accumulators directly ---
    const int gl = lane >> 2;          // 0..7
    const int tl = lane & 3;           // 0..3
    #pragma unroll
    for (int mt = 0; mt < 2; ++mt) {
        #pragma unroll
        for (int nt = 0; nt < 8; ++nt) {
            const int row0 = m0 + wm*32 + mt*16 + gl;
            const int colg = n0 + wn*64 + nt*8 + 2*tl;
            if (mode == 0) {
                const int head = colg >> 6;        // 0..47
                const int proj = head >> 4;        // 0=q 1=k 2=v
                const int h    = head & 15;
                const int d0c  = colg & 63;
                float* op = (proj == 0) ? g_q : (proj == 1) ? g_k : g_v;
                const float2 bia = *(const float2*)&g_bqkv[colg];
                #pragma unroll
                for (int rr = 0; rr < 2; ++rr) {
                    const int m = row0 + rr*8;
                    const int b_ = m >> 11, t = m & 2047;
                    float2 o;
                    o.x = acc[mt][nt][2*rr+0] + bia.x;
                    o.y = acc[mt][nt][2*rr+1] + bia.y;
                    *(float2*)(op + (((size_t)(b_*HH + h) * TT + t) * DD + d0c)) = o;
                }
            } else {
                const float2 bia = *(const float2*)&bias1[colg];
                #pragma unroll
                for (int rr = 0; rr < 2; ++rr) {
                    const int m = row0 + rr*8;
                    float2 o;
                    o.x = acc[mt][nt][2*rr+0] + bia.x;
                    o.y = acc[mt][nt][2*rr+1] + bia.y;
                    *(float2*)(outf + (size_t)m * CC + colg) = o;
                }
            }
        }
    }
}

// ---------------------------------------------------------------------------
// Flash attention, fp32, online softmax (unchanged — passing at rel 1e-6).
// ---------------------------------------------------------------------------
#define FLASH_SMEM_FLOATS (2*64*68 + 64*64)

__global__ __launch_bounds__(256) void flash64()
{
    extern __shared__ float sm[];
    float* Qt   = sm;              // [d][q], stride 68
    float* KtPs = sm + 64*68;      // Kt: [d][k]; Ps: [q][k], stride 68
    float* Vs   = sm + 2*64*68;    // [k][d], stride 64

    const int tid = threadIdx.x;
    const int tr  = tid >> 4;
    const int tc  = tid & 15;
    const int q0  = blockIdx.x << 6;
    const int bh  = blockIdx.y;

    const float* qg = g_q + ((size_t)bh * TT + q0) * DD;
    const float* kg = g_k + (size_t)bh * TT * DD;
    const float* vg = g_v + (size_t)bh * TT * DD;

    const int tl = tid >> 2;
    const int d4 = (tid & 3) << 2;

    #pragma unroll
    for (int dd = 0; dd < 64; dd += 16) {
        float4 v = *(const float4*)(qg + tl * DD + dd + d4);
        Qt[(dd+d4+0)*68 + tl] = v.x * 0.125f;
        Qt[(dd+d4+1)*68 + tl] = v.y * 0.125f;
        Qt[(dd+d4+2)*68 + tl] = v.z * 0.125f;
        Qt[(dd+d4+3)*68 + tl] = v.w * 0.125f;
    }

    float m_run[4], l_run[4], acc[4][4];
    #pragma unroll
    for (int i = 0; i < 4; i++) {
        m_run[i] = -1e30f;
        l_run[i] = 0.f;
        #pragma unroll
        for (int j = 0; j < 4; j++) acc[i][j] = 0.f;
    }

    const int jmax = q0 >> 6;
    for (int jt = 0; jt <= jmax; jt++) {
        __syncthreads();
        #pragma unroll
        for (int dd = 0; dd < 64; dd += 16) {
            float4 kv = *(const float4*)(kg + (size_t)((jt<<6) + tl) * DD + dd + d4);
            KtPs[(dd+d4+0)*68 + tl] = kv.x;
            KtPs[(dd+d4+1)*68 + tl] = kv.y;
            KtPs[(dd+d4+2)*68 + tl] = kv.z;
            KtPs[(dd+d4+3)*68 + tl] = kv.w;
            float4 vv = *(const float4*)(vg + (size_t)((jt<<6) + tl) * DD + dd + d4);
            *(float4*)&Vs[tl*64 + dd + d4] = vv;
        }
        __syncthreads();

        float s[4][4] = {};
        #pragma unroll 16
        for (int d = 0; d < 64; d++) {
            float4 a = *(const float4*)&Qt[d*68 + (tr << 2)];
            float4 b = *(const float4*)&KtPs[d*68 + (tc << 2)];
            float aa[4] = {a.x, a.y, a.z, a.w};
            float bbv[4] = {b.x, b.y, b.z, b.w};
            #pragma unroll
            for (int i = 0; i < 4; i++)
                #pragma unroll
                for (int j = 0; j < 4; j++)
                    s[i][j] += aa[i] * bbv[j];
        }

        if (jt == jmax) {
            #pragma unroll
            for (int i = 0; i < 4; i++) {
                int qgl = q0 + (tr << 2) + i;
                #pragma unroll
                for (int j = 0; j < 4; j++) {
                    int kgl = (jt << 6) + (tc << 2) + j;
                    if (kgl > qgl) s[i][j] = -1e30f;
                }
            }
        }

        float mnew[4], rs[4], p[4][4];
        #pragma unroll
        for (int i = 0; i < 4; i++) {
            float rm = fmaxf(fmaxf(s[i][0], s[i][1]), fmaxf(s[i][2], s[i][3]));
            rm = fmaxf(rm, __shfl_xor_sync(0xffffffffu, rm, 8, 16));
            rm = fmaxf(rm, __shfl_xor_sync(0xffffffffu, rm, 4, 16));
            rm = fmaxf(rm, __shfl_xor_sync(0xffffffffu, rm, 2, 16));
            rm = fmaxf(rm, __shfl_xor_sync(0xffffffffu, rm, 1, 16));
            mnew[i] = fmaxf(m_run[i], rm);
            float sum = 0.f;
            #pragma unroll
            for (int j = 0; j < 4; j++) {
                p[i][j] = __expf(s[i][j] - mnew[i]);
                sum += p[i][j];
            }
            sum += __shfl_xor_sync(0xffffffffu, sum, 8, 16);
            sum += __shfl_xor_sync(0xffffffffu, sum, 4, 16);
            sum += __shfl_xor_sync(0xffffffffu, sum, 2, 16);
            sum += __shfl_xor_sync(0xffffffffu, sum, 1, 16);
            rs[i] = sum;
        }

        __syncthreads();

        #pragma unroll
        for (int i = 0; i < 4; i++) {
            float4 pv = make_float4(p[i][0], p[i][1], p[i][2], p[i][3]);
            *(float4*)&KtPs[((tr << 2) + i) * 68 + (tc << 2)] = pv;
        }

        __syncthreads();

        #pragma unroll
        for (int i = 0; i < 4; i++) {
            float alpha = __expf(m_run[i] - mnew[i]);
            m_run[i] = mnew[i];
            l_run[i] = l_run[i] * alpha + rs[i];
            #pragma unroll
            for (int j = 0; j < 4; j++) acc[i][j] *= alpha;
        }
        #pragma unroll 16
        for (int kk = 0; kk < 64; kk++) {
            float aa[4];
            #pragma unroll
            for (int i = 0; i < 4; i++)
                aa[i] = KtPs[((tr << 2) + i) * 68 + kk];
            float4 b = *(const float4*)&Vs[kk*64 + (tc << 2)];
            float bbv[4] = {b.x, b.y, b.z, b.w};
            #pragma unroll
            for (int i = 0; i < 4; i++)
                #pragma unroll
                for (int j = 0; j < 4; j++)
                    acc[i][j] += aa[i] * bbv[j];
        }
    }

    const int b = bh >> 4;
    const int h = bh & 15;
    #pragma unroll
    for (int i = 0; i < 4; i++) {
        float inv = 1.f / l_run[i];
        int t = q0 + (tr << 2) + i;
        float4 o;
        o.x = acc[i][0] * inv;
        o.y = acc[i][1] * inv;
        o.z = acc[i][2] * inv;
        o.w = acc[i][3] * inv;
        *(float4*)&g_y[((size_t)(b*TT + t)) * CC + h*DD + (tc << 2)] = o;
    }
}

// ---------------------------------------------------------------------------

extern "C" void kernel_launch(void* const* d_in, const int* in_sizes, int n_in,
                              void* d_out, int out_size)
{
    const float* x  = (const float*)d_in[0];
    const float* Wq = (const float*)d_in[1];
    const float* bq = (const float*)d_in[2];
    const float* Wk = (const float*)d_in[3];
    const float* bk = (const float*)d_in[4];
    const float* Wv = (const float*)d_in[5];
    const float* bv = (const float*)d_in[6];
    const float* Wo = (const float*)d_in[7];
    const float* bo = (const float*)d_in[8];
    float* out = (float*)d_out;

    // 0) fp32 -> bf16 hi/lo splits (8M elements) + bias concat
    prep_split<<<(8*1024*1024)/256, 256>>>(Wq, Wk, Wv, Wo, x);
    prep_bias<<<12, 256>>>(bq, bk, bv);

    // 1) fused QKV projection on tensor cores (mma.sync) -> g_q/g_k/g_v
    cudaFuncSetAttribute(gemm_tc, cudaFuncAttributeMaxDynamicSharedMemorySize,
                         GEMM_SMEM);
    gemm_tc<<<dim3(3*CC/128, MM/128), 256, GEMM_SMEM>>>(0, nullptr, nullptr);

    // 2) causal flash attention -> g_y
    const int fsmem = FLASH_SMEM_FLOATS * (int)sizeof(float);
    cudaFuncSetAttribute(flash64, cudaFuncAttributeMaxDynamicSharedMemorySize,
                         fsmem);
    flash64<<<dim3(TT/64, BB*HH), 256, fsmem>>>();

    // 3) y -> bf16 hi/lo, output projection (mma.sync) -> d_out
    prep_y<<<(MM*CC)/256, 256>>>();
    gemm_tc<<<dim3(CC/128, MM/128), 256, GEMM_SMEM>>>(1, bo, out);
}

// round 6
// speedup vs baseline: 3.1486x; 1.9023x over previous
#include <cuda_runtime.h>
#include <cuda_bf16.h>
#include <cstdint>
#include <math.h>

#define BB 2
#define TT 2048
#define CC 1024
#define HH 16
#define DD 64
#define MM (BB*TT)   // 4096 rows

// ---------------------------------------------------------------------------
// Scratch (__device__ globals; allocation-free rule)
// ---------------------------------------------------------------------------
__device__ __nv_bfloat16 g_qhi[BB*HH*TT*DD], g_qlo[BB*HH*TT*DD];  // [B,H,T,D]
__device__ __nv_bfloat16 g_khi[BB*HH*TT*DD], g_klo[BB*HH*TT*DD];
__device__ __nv_bfloat16 g_vhi[BB*HH*TT*DD], g_vlo[BB*HH*TT*DD];

__device__ __nv_bfloat16 g_xhi[MM*CC], g_xlo[MM*CC];        // x split
__device__ __nv_bfloat16 g_whi[3*CC*CC], g_wlo[3*CC*CC];    // Wq|Wk|Wv concat
__device__ __nv_bfloat16 g_wohi[CC*CC], g_wolo[CC*CC];      // Wo
__device__ __nv_bfloat16 g_yhi[MM*CC], g_ylo[MM*CC];        // y split [B,T,C]
__device__ float g_bqkv[3*CC];                               // bq|bk|bv concat

// Q pre-scale: 1/sqrt(64) * log2(e)  (softmax done in base-2)
#define QSCALE (0.125f * 1.4426950408889634f)

// ---------------------------------------------------------------------------
// Helpers: ldmatrix / mma.sync / cp.async (baseline sm_80+)
// ---------------------------------------------------------------------------
__device__ __forceinline__ uint32_t smem_to_u32(const void* p) {
    uint32_t a;
    asm("{ .reg .u64 t; cvta.to.shared.u64 t, %1; cvt.u32.u64 %0, t; }"
        : "=r"(a) : "l"(p));
    return a;
}
__device__ __forceinline__ void ldsm_x4(uint32_t* r, uint32_t addr) {
    asm volatile("ldmatrix.sync.aligned.m8n8.x4.shared.b16 {%0,%1,%2,%3}, [%4];"
        : "=r"(r[0]), "=r"(r[1]), "=r"(r[2]), "=r"(r[3]) : "r"(addr));
}
__device__ __forceinline__ void ldsm_x4_t(uint32_t* r, uint32_t addr) {
    asm volatile("ldmatrix.sync.aligned.m8n8.x4.trans.shared.b16 {%0,%1,%2,%3}, [%4];"
        : "=r"(r[0]), "=r"(r[1]), "=r"(r[2]), "=r"(r[3]) : "r"(addr));
}
__device__ __forceinline__ void mma_bf16(float* d, const uint32_t* a,
                                         const uint32_t* b) {
    asm volatile(
        "mma.sync.aligned.m16n8k16.row.col.f32.bf16.bf16.f32 "
        "{%0,%1,%2,%3}, {%4,%5,%6,%7}, {%8,%9}, {%0,%1,%2,%3};"
        : "+f"(d[0]), "+f"(d[1]), "+f"(d[2]), "+f"(d[3])
        : "r"(a[0]), "r"(a[1]), "r"(a[2]), "r"(a[3]), "r"(b[0]), "r"(b[1]));
}
__device__ __forceinline__ void cp16(uint32_t saddr, const void* g) {
    asm volatile("cp.async.cg.shared.global [%0], [%1], 16;"
        :: "r"(saddr), "l"(g) : "memory");
}
#define CP_COMMIT()  asm volatile("cp.async.commit_group;" ::: "memory")
#define CP_WAIT1()   asm volatile("cp.async.wait_group 1;" ::: "memory")
#define CP_WAIT0()   asm volatile("cp.async.wait_group 0;" ::: "memory")

#define SMEM_SWIZZLE_128B(byte_offset) \
    ((byte_offset) ^ (((byte_offset) >> 3) & 0x70))

__device__ __forceinline__ float exp2a(float x) {
    float y; asm("ex2.approx.f32 %0, %1;" : "=f"(y) : "f"(x)); return y;
}
__device__ __forceinline__ uint32_t pack_bf16x2(float lo, float hi) {
    uint32_t r;
    asm("cvt.rn.bf16x2.f32 %0, %1, %2;" : "=r"(r) : "f"(hi), "f"(lo));
    return r;
}
__device__ __forceinline__ float2 bf16x2_to_f2(uint32_t u) {
    __nv_bfloat162 h = *reinterpret_cast<__nv_bfloat162*>(&u);
    return __bfloat1622float2(h);
}

// ---------------------------------------------------------------------------
// Prep: fp32 -> bf16 hi/lo splits, bias concat.
// ---------------------------------------------------------------------------
__global__ __launch_bounds__(256) void prep_split(
    const float* __restrict__ Wq, const float* __restrict__ Wk,
    const float* __restrict__ Wv, const float* __restrict__ Wo,
    const float* __restrict__ x)
{
    const int i = blockIdx.x * 256 + threadIdx.x;   // 0 .. 8M-1
    const int WQKV = 3*CC*CC, WO = CC*CC;
    float v;
    __nv_bfloat16 *hi, *lo;
    int j;
    if (i < WQKV) {
        const float* s = (i < CC*CC) ? Wq : (i < 2*CC*CC) ? Wk : Wv;
        v = s[i & (CC*CC - 1)];
        hi = g_whi; lo = g_wlo; j = i;
    } else if (i < WQKV + WO) {
        j = i - WQKV;
        v = Wo[j];
        hi = g_wohi; lo = g_wolo;
    } else {
        j = i - WQKV - WO;      // 0 .. 4M-1
        v = x[j];
        hi = g_xhi; lo = g_xlo;
    }
    __nv_bfloat16 h = __float2bfloat16(v);
    hi[j] = h;
    lo[j] = __float2bfloat16(v - __bfloat162float(h));
}

__global__ void prep_bias(const float* __restrict__ bq,
                          const float* __restrict__ bk,
                          const float* __restrict__ bv)
{
    int i = blockIdx.x * 256 + threadIdx.x;
    if (i < 3*CC)
        g_bqkv[i] = (i < CC) ? bq[i] : (i < 2*CC) ? bk[i-CC] : bv[i-2*CC];
}

// ---------------------------------------------------------------------------
// mma.sync GEMM: 128x128 tile of A[M,1024] @ B[N,1024]^T, bf16 hi/lo 3-term.
// mode 0: A=x, B=WqWkWv, scatter bf16 hi/lo q/k/v (+bias, Q scaled).
// mode 1: A=y(hi/lo), B=Wo, write d_out fp32 (+bo).
// ---------------------------------------------------------------------------
#define CHUNK_K   64
#define NCHUNK    (CC / CHUNK_K)      // 16
#define BUF_BYTES (128*64*2)          // 16 KB per operand buffer
#define STAGE_BYTES (4*BUF_BYTES)     // 64 KB
#define OFF_AH 0
#define OFF_AL (1*BUF_BYTES)
#define OFF_BH (2*BUF_BYTES)
#define OFF_BL (3*BUF_BYTES)
#define GEMM_SMEM (2*STAGE_BYTES + 1024)

__global__ __launch_bounds__(256, 1) void gemm_tc(
    int mode, const float* __restrict__ bias1, float* __restrict__ outf)
{
    extern __shared__ char smem[];
    const uint32_t smem_u32 = smem_to_u32(smem);
    const uint32_t tile_u32 = (smem_u32 + 1023) & ~1023u;

    const int tid  = threadIdx.x;
    const int wid  = tid >> 5;
    const int lane = tid & 31;
    const int wm   = wid >> 1;          // 0..3 (M)
    const int wn   = wid & 1;           // 0..1 (N)
    const int m0   = blockIdx.y << 7;
    const int n0   = blockIdx.x << 7;

    const __nv_bfloat16 *Ah, *Al, *Bh, *Bl;
    if (mode == 0) { Ah = g_xhi; Al = g_xlo; Bh = g_whi;  Bl = g_wlo;  }
    else           { Ah = g_yhi; Al = g_ylo; Bh = g_wohi; Bl = g_wolo; }

    auto issue_chunk = [&](int c, int s) {
        const int kc = c * CHUNK_K;
        const uint32_t st = tile_u32 + s * STAGE_BYTES;
        #pragma unroll
        for (int i = 0; i < 4; i++) {
            int idx = tid + i*256;           // 0..1023
            int r   = idx >> 3;              // tile row 0..127
            int g   = idx & 7;               // 16B group in row
            uint32_t so = SMEM_SWIZZLE_128B((uint32_t)(r*128 + g*16));
            size_t aoff = (size_t)(m0 + r) * CC + kc + g*8;
            size_t boff = (size_t)(n0 + r) * CC + kc + g*8;
            cp16(st + OFF_AH + so, Ah + aoff);
            cp16(st + OFF_AL + so, Al + aoff);
            cp16(st + OFF_BH + so, Bh + boff);
            cp16(st + OFF_BL + so, Bl + boff);
        }
        CP_COMMIT();
    };

    float acc[2][8][4];
    #pragma unroll
    for (int mt = 0; mt < 2; mt++)
        #pragma unroll
        for (int nt = 0; nt < 8; nt++)
            #pragma unroll
            for (int e = 0; e < 4; e++) acc[mt][nt][e] = 0.f;

    issue_chunk(0, 0);
    issue_chunk(1, 1);

    for (int c = 0; c < NCHUNK; ++c) {
        const int s = c & 1;
        if (c + 1 < NCHUNK) { CP_WAIT1(); } else { CP_WAIT0(); }
        __syncthreads();

        const uint32_t sAh = tile_u32 + s*STAGE_BYTES + OFF_AH;
        const uint32_t sAl = tile_u32 + s*STAGE_BYTES + OFF_AL;
        const uint32_t sBh = tile_u32 + s*STAGE_BYTES + OFF_BH;
        const uint32_t sBl = tile_u32 + s*STAGE_BYTES + OFF_BL;

        #pragma unroll
        for (int ks = 0; ks < 4; ++ks) {
            uint32_t ah[2][4], al[2][4];
            #pragma unroll
            for (int mt = 0; mt < 2; ++mt) {
                int r = wm*32 + mt*16 + (lane & 15);
                int g = ks*2 + (lane >> 4);
                uint32_t off = SMEM_SWIZZLE_128B((uint32_t)(r*128 + g*16));
                ldsm_x4(ah[mt], sAh + off);
                ldsm_x4(al[mt], sAl + off);
            }
            #pragma unroll
            for (int np = 0; np < 4; ++np) {
                int n = wn*64 + np*16 + ((lane >> 4) << 3) + (lane & 7);
                int g = ks*2 + ((lane >> 3) & 1);
                uint32_t off = SMEM_SWIZZLE_128B((uint32_t)(n*128 + g*16));
                uint32_t bh[4], bl[4];
                ldsm_x4(bh, sBh + off);
                ldsm_x4(bl, sBl + off);
                #pragma unroll
                for (int mt = 0; mt < 2; ++mt) {
                    mma_bf16(acc[mt][2*np],   ah[mt], bh);
                    mma_bf16(acc[mt][2*np+1], ah[mt], bh + 2);
                    mma_bf16(acc[mt][2*np],   ah[mt], bl);
                    mma_bf16(acc[mt][2*np+1], ah[mt], bl + 2);
                    mma_bf16(acc[mt][2*np],   al[mt], bh);
                    mma_bf16(acc[mt][2*np+1], al[mt], bh + 2);
                }
            }
        }

        if (c + 2 < NCHUNK) {
            __syncthreads();
            issue_chunk(c + 2, s);
        }
    }

    // --- epilogue ---
    const int gl = lane >> 2;          // 0..7
    const int tl = lane & 3;           // 0..3
    #pragma unroll
    for (int mt = 0; mt < 2; ++mt) {
        #pragma unroll
        for (int nt = 0; nt < 8; ++nt) {
            const int row0 = m0 + wm*32 + mt*16 + gl;
            const int colg = n0 + wn*64 + nt*8 + 2*tl;
            if (mode == 0) {
                const int head = colg >> 6;        // 0..47
                const int proj = head >> 4;        // 0=q 1=k 2=v
                const int h    = head & 15;
                const int d0c  = colg & 63;
                __nv_bfloat16 *hiP, *loP;
                if (proj == 0)      { hiP = g_qhi; loP = g_qlo; }
                else if (proj == 1) { hiP = g_khi; loP = g_klo; }
                else                { hiP = g_vhi; loP = g_vlo; }
                const float2 bia = *(const float2*)&g_bqkv[colg];
                #pragma unroll
                for (int rr = 0; rr < 2; ++rr) {
                    const int m = row0 + rr*8;
                    const int b_ = m >> 11, t = m & 2047;
                    float v0 = acc[mt][nt][2*rr+0] + bia.x;
                    float v1 = acc[mt][nt][2*rr+1] + bia.y;
                    if (proj == 0) { v0 *= QSCALE; v1 *= QSCALE; }
                    uint32_t hp = pack_bf16x2(v0, v1);
                    float2 hf = bf16x2_to_f2(hp);
                    uint32_t lp = pack_bf16x2(v0 - hf.x, v1 - hf.y);
                    size_t off = ((size_t)(b_*HH + h) * TT + t) * DD + d0c;
                    *(uint32_t*)(hiP + off) = hp;
                    *(uint32_t*)(loP + off) = lp;
                }
            } else {
                const float2 bia = *(const float2*)&bias1[colg];
                #pragma unroll
                for (int rr = 0; rr < 2; ++rr) {
                    const int m = row0 + rr*8;
                    float2 o;
                    o.x = acc[mt][nt][2*rr+0] + bia.x;
                    o.y = acc[mt][nt][2*rr+1] + bia.y;
                    *(float2*)(outf + (size_t)m * CC + colg) = o;
                }
            }
        }
    }
}

// ---------------------------------------------------------------------------
// Tensor-core flash attention: 128-query x 64-key tiles, bf16 hi/lo 3-term,
// fp32 softmax in registers, base-2 exp (Q pre-scaled by log2e/8).
// 8 warps x 16 q-rows; double-buffered cp.async K/V stages.
// R6 FIX: Q tile load covers all 128 rows x (hi+lo) = 2048 16B chunks.
// ---------------------------------------------------------------------------
#define F_SMEM (32768 + 65536)   // Q(hi+lo) 32KB + 2 stages x (K/V hi/lo) 32KB

__global__ __launch_bounds__(256, 1) void flash_tc()
{
    extern __shared__ char fsm[];
    const uint32_t sb  = smem_to_u32(fsm);
    const uint32_t sQh = sb, sQl = sb + 16384;

    const int tid = threadIdx.x, wid = tid >> 5, lane = tid & 31;
    const int gl = lane >> 2, tl = lane & 3;
    const int jq = (int)gridDim.x - 1 - (int)blockIdx.x;   // heavy tiles first
    const int q0 = jq << 7;
    const int bh = blockIdx.y;
    const size_t hb = (size_t)bh * TT * DD;
    const __nv_bfloat16 *qhp = g_qhi + hb + (size_t)q0 * DD;
    const __nv_bfloat16 *qlp = g_qlo + hb + (size_t)q0 * DD;
    const __nv_bfloat16 *khp = g_khi + hb, *klp = g_klo + hb;
    const __nv_bfloat16 *vhp = g_vhi + hb, *vlp = g_vlo + hb;
    const int ntiles = 2*jq + 2;

    // --- Q tile (hi+lo): 128 rows x 8 chunks x 2 buffers = 2048 chunks ---
    #pragma unroll
    for (int i = 0; i < 8; i++) {
        int idx = tid + i*256;              // 0..2047
        int buf = idx >> 10;                // 0 hi, 1 lo
        int rc = idx & 1023; int r = rc >> 3, c = rc & 7;
        uint32_t so = SMEM_SWIZZLE_128B((uint32_t)(r*128 + c*16));
        cp16((buf ? sQl : sQh) + so, (buf ? qlp : qhp) + (size_t)r*DD + c*8);
    }
    CP_COMMIT();

    auto issue_kv = [&](int kt, int s) {
        const uint32_t st = sb + 32768 + s*32768;
        const int r0 = kt << 6;
        #pragma unroll
        for (int i = 0; i < 8; i++) {
            int idx = tid + i*256;          // 0..2047
            int buf = idx >> 9;             // 0 khi,1 klo,2 vhi,3 vlo
            int rc = idx & 511; int r = rc >> 3, c = rc & 7;
            uint32_t so = SMEM_SWIZZLE_128B((uint32_t)(r*128 + c*16));
            const __nv_bfloat16* src =
                (buf == 0 ? khp : buf == 1 ? klp : buf == 2 ? vhp : vlp)
                + (size_t)(r0 + r) * DD + c*8;
            cp16(st + buf*8192 + so, src);
        }
        CP_COMMIT();
    };
    issue_kv(0, 0);
    issue_kv(1, 1);

    CP_WAIT1();              // Q + stage0 complete
    __syncthreads();

    // --- Q fragments (persistent) ---
    const int qrow = wid << 4;
    uint32_t qfh[4][4], qfl[4][4];
    #pragma unroll
    for (int dc = 0; dc < 4; dc++) {
        uint32_t so = SMEM_SWIZZLE_128B((uint32_t)(
            (qrow + (lane & 15))*128 + (dc*16 + ((lane >> 4) << 3))*2));
        ldsm_x4(qfh[dc], sQh + so);
        ldsm_x4(qfl[dc], sQl + so);
    }

    float m_run[2] = {-1e30f, -1e30f};
    float l_run[2] = {0.f, 0.f};
    float oacc[8][4];
    #pragma unroll
    for (int f = 0; f < 8; f++)
        #pragma unroll
        for (int e = 0; e < 4; e++) oacc[f][e] = 0.f;

    for (int kt = 0; kt < ntiles; kt++) {
        const int s = kt & 1;
        if (kt + 1 < ntiles) { CP_WAIT1(); } else { CP_WAIT0(); }
        __syncthreads();

        const bool active = (q0 + qrow + 15) >= (kt << 6);
        if (active) {
            const uint32_t st = sb + 32768 + s*32768;

            // ---- S = Q @ K^T (3-term) ----
            float sacc[8][4] = {};
            #pragma unroll
            for (int dc = 0; dc < 4; dc++) {
                #pragma unroll
                for (int ng = 0; ng < 4; ng++) {
                    uint32_t so = SMEM_SWIZZLE_128B((uint32_t)(
                        ((ng<<4) + (lane & 7) + ((lane >> 4) << 3))*128 +
                        ((dc<<4) + ((lane >> 3) & 1)*8)*2));
                    uint32_t kfh[4], kfl[4];
                    ldsm_x4(kfh, st + so);
                    ldsm_x4(kfl, st + 8192 + so);
                    mma_bf16(sacc[2*ng],   qfh[dc], kfh);
                    mma_bf16(sacc[2*ng+1], qfh[dc], kfh + 2);
                    mma_bf16(sacc[2*ng],   qfh[dc], kfl);
                    mma_bf16(sacc[2*ng+1], qfh[dc], kfl + 2);
                    mma_bf16(sacc[2*ng],   qfl[dc], kfh);
                    mma_bf16(sacc[2*ng+1], qfl[dc], kfh + 2);
                }
            }

            // ---- causal mask (diagonal tiles only) ----
            if (kt >= 2*jq) {
                const int r0g = q0 + qrow + gl;
                #pragma unroll
                for (int f = 0; f < 8; f++) {
                    const int kc0 = (kt << 6) + (f << 3) + (tl << 1);
                    if (kc0     > r0g)     sacc[f][0] = -1e30f;
                    if (kc0 + 1 > r0g)     sacc[f][1] = -1e30f;
                    if (kc0     > r0g + 8) sacc[f][2] = -1e30f;
                    if (kc0 + 1 > r0g + 8) sacc[f][3] = -1e30f;
                }
            }

            // ---- online softmax (base 2) ----
            float mx0 = m_run[0], mx1 = m_run[1];
            #pragma unroll
            for (int f = 0; f < 8; f++) {
                mx0 = fmaxf(mx0, fmaxf(sacc[f][0], sacc[f][1]));
                mx1 = fmaxf(mx1, fmaxf(sacc[f][2], sacc[f][3]));
            }
            mx0 = fmaxf(mx0, __shfl_xor_sync(0xffffffffu, mx0, 1));
            mx0 = fmaxf(mx0, __shfl_xor_sync(0xffffffffu, mx0, 2));
            mx1 = fmaxf(mx1, __shfl_xor_sync(0xffffffffu, mx1, 1));
            mx1 = fmaxf(mx1, __shfl_xor_sync(0xffffffffu, mx1, 2));
            const float a0 = exp2a(m_run[0] - mx0);
            const float a1 = exp2a(m_run[1] - mx1);
            m_run[0] = mx0; m_run[1] = mx1;

            float sum0 = 0.f, sum1 = 0.f;
            uint32_t pAh[8], pBh[8], pAl[8], pBl[8];
            #pragma unroll
            for (int f = 0; f < 8; f++) {
                float p0 = exp2a(sacc[f][0] - mx0);
                float p1 = exp2a(sacc[f][1] - mx0);
                float p2 = exp2a(sacc[f][2] - mx1);
                float p3 = exp2a(sacc[f][3] - mx1);
                sum0 += p0 + p1; sum1 += p2 + p3;
                uint32_t h01 = pack_bf16x2(p0, p1);
                uint32_t h23 = pack_bf16x2(p2, p3);
                float2 f01 = bf16x2_to_f2(h01);
                float2 f23 = bf16x2_to_f2(h23);
                pAh[f] = h01; pBh[f] = h23;
                pAl[f] = pack_bf16x2(p0 - f01.x, p1 - f01.y);
                pBl[f] = pack_bf16x2(p2 - f23.x, p3 - f23.y);
            }
            sum0 += __shfl_xor_sync(0xffffffffu, sum0, 1);
            sum0 += __shfl_xor_sync(0xffffffffu, sum0, 2);
            sum1 += __shfl_xor_sync(0xffffffffu, sum1, 1);
            sum1 += __shfl_xor_sync(0xffffffffu, sum1, 2);
            l_run[0] = l_run[0]*a0 + sum0;
            l_run[1] = l_run[1]*a1 + sum1;
            #pragma unroll
            for (int f = 0; f < 8; f++) {
                oacc[f][0] *= a0; oacc[f][1] *= a0;
                oacc[f][2] *= a1; oacc[f][3] *= a1;
            }

            // ---- O += P @ V (3-term; V via ldmatrix.trans) ----
            #pragma unroll
            for (int kc = 0; kc < 4; kc++) {
                uint32_t Ahh[4] = {pAh[2*kc], pBh[2*kc], pAh[2*kc+1], pBh[2*kc+1]};
                uint32_t All[4] = {pAl[2*kc], pBl[2*kc], pAl[2*kc+1], pBl[2*kc+1]};
                #pragma unroll
                for (int dg = 0; dg < 4; dg++) {
                    uint32_t so = SMEM_SWIZZLE_128B((uint32_t)(
                        ((kc<<4) + (lane & 7) + ((lane >> 3) & 1)*8)*128 +
                        ((dg<<4) + (lane >> 4)*8)*2));
                    uint32_t vfh[4], vfl[4];
                    ldsm_x4_t(vfh, st + 16384 + so);
                    ldsm_x4_t(vfl, st + 24576 + so);
                    mma_bf16(oacc[2*dg],   Ahh, vfh);
                    mma_bf16(oacc[2*dg+1], Ahh, vfh + 2);
                    mma_bf16(oacc[2*dg],   Ahh, vfl);
                    mma_bf16(oacc[2*dg+1], Ahh, vfl + 2);
                    mma_bf16(oacc[2*dg],   All, vfh);
                    mma_bf16(oacc[2*dg+1], All, vfh + 2);
                }
            }
        }

        __syncthreads();
        if (kt + 2 < ntiles) issue_kv(kt + 2, s);
    }

    // ---- epilogue: normalize, split hi/lo, write y [B,T,C] ----
    const float inv0 = 1.f / l_run[0];
    const float inv1 = 1.f / l_run[1];
    const int b_ = bh >> 4, h = bh & 15;
    const int t0 = q0 + qrow + gl, t1 = t0 + 8;
    #pragma unroll
    for (int f = 0; f < 8; f++) {
        const int col = h*DD + (f << 3) + (tl << 1);
        {
            float y0 = oacc[f][0] * inv0, y1 = oacc[f][1] * inv0;
            uint32_t hp = pack_bf16x2(y0, y1);
            float2 hf = bf16x2_to_f2(hp);
            uint32_t lp = pack_bf16x2(y0 - hf.x, y1 - hf.y);
            size_t off = (size_t)(b_*TT + t0) * CC + col;
            *(uint32_t*)(g_yhi + off) = hp;
            *(uint32_t*)(g_ylo + off) = lp;
        }
        {
            float y2 = oacc[f][2] * inv1, y3 = oacc[f][3] * inv1;
            uint32_t hp = pack_bf16x2(y2, y3);
            float2 hf = bf16x2_to_f2(hp);
            uint32_t lp = pack_bf16x2(y2 - hf.x, y3 - hf.y);
            size_t off = (size_t)(b_*TT + t1) * CC + col;
            *(uint32_t*)(g_yhi + off) = hp;
            *(uint32_t*)(g_ylo + off) = lp;
        }
    }
}

// ---------------------------------------------------------------------------

extern "C" void kernel_launch(void* const* d_in, const int* in_sizes, int n_in,
                              void* d_out, int out_size)
{
    const float* x  = (const float*)d_in[0];
    const float* Wq = (const float*)d_in[1];
    const float* bq = (const float*)d_in[2];
    const float* Wk = (const float*)d_in[3];
    const float* bk = (const float*)d_in[4];
    const float* Wv = (const float*)d_in[5];
    const float* bv = (const float*)d_in[6];
    const float* Wo = (const float*)d_in[7];
    const float* bo = (const float*)d_in[8];
    float* out = (float*)d_out;

    // 0) fp32 -> bf16 hi/lo splits + bias concat
    prep_split<<<(8*1024*1024)/256, 256>>>(Wq, Wk, Wv, Wo, x);
    prep_bias<<<12, 256>>>(bq, bk, bv);

    // 1) fused QKV projection -> bf16 hi/lo q/k/v (Q pre-scaled)
    cudaFuncSetAttribute(gemm_tc, cudaFuncAttributeMaxDynamicSharedMemorySize,
                         GEMM_SMEM);
    gemm_tc<<<dim3(3*CC/128, MM/128), 256, GEMM_SMEM>>>(0, nullptr, nullptr);

    // 2) tensor-core causal flash attention -> y hi/lo
    cudaFuncSetAttribute(flash_tc, cudaFuncAttributeMaxDynamicSharedMemorySize,
                         F_SMEM);
    flash_tc<<<dim3(TT/128, BB*HH), 256, F_SMEM>>>();

    // 3) output projection -> d_out
    gemm_tc<<<dim3(CC/128, MM/128), 256, GEMM_SMEM>>>(1, bo, out);
}